// round 10
// baseline (speedup 1.0000x reference)
#include <cuda_runtime.h>
#include <math.h>

#define BB   32
#define LL   1024
#define DG   1024
#define HH   1024
#define OUTW 2048
#define BL   (BB * LL)          // 32768 rows

__device__ float        g_part[4 * BL];   // split-K partials [hq][b*LL+l]
__device__ float        g_gate[BL];       // final sigmoid gate
__device__ unsigned int g_cnt[128];       // per-(bg,lt) arrival counters (self-resetting)

// ---------------------------------------------------------------------------
// Gate: split-K-4 GEMM + in-kernel fixup.
// Grid 512 = (32 l-tiles) x (4 batch groups) x (4 h-quarters), 512 threads.
// Each block: 8 batches x 32 l x 256 h. Warp covers 16 h, ALL 16 W loads
// issued before any FMA (MLP=16). Last-arriving block of each (bg,lt) group
// sums the 4 partials + bias, applies sigmoid, writes g_gate.
// ---------------------------------------------------------------------------
__global__ __launch_bounds__(512, 2)
void gate_kernel(const float* __restrict__ query,
                 const float* __restrict__ W,
                 const float* __restrict__ bias)
{
    __shared__ float sq[8 * 256];         // 8 KiB query slice
    __shared__ float red[16][8][32];      // 16 KiB
    __shared__ int   s_last;

    const int tid  = threadIdx.x;
    const int warp = tid >> 5;
    const int lane = tid & 31;
    const int bid  = blockIdx.x;
    const int lt   = bid & 31;            // l-tile
    const int bg   = (bid >> 5) & 3;      // batch group
    const int hq   = bid >> 7;            // h-quarter

    // Stage 8 x 256 query slice (512 float4, one per thread)
    {
        const int b = tid >> 6;
        const int j = tid & 63;
        ((float4*)sq)[b * 64 + j] =
            __ldg((const float4*)query + (bg * 8 + b) * (HH / 4) + hq * 64 + j);
    }
    __syncthreads();

    const int l  = lt * 32 + lane;
    const int h0 = hq * 256 + warp * 16;

    // All 16 W loads up-front: MLP=16
    float w[16];
    #pragma unroll
    for (int j = 0; j < 16; ++j)
        w[j] = __ldg(&W[(h0 + j) * LL + l]);

    float acc[8];
    #pragma unroll
    for (int b = 0; b < 8; ++b) acc[b] = 0.f;

    #pragma unroll
    for (int b = 0; b < 8; ++b) {
        const float* qb = sq + b * 256 + warp * 16;
        #pragma unroll
        for (int j = 0; j < 16; ++j)
            acc[b] = fmaf(qb[j], w[j], acc[b]);
    }

    #pragma unroll
    for (int b = 0; b < 8; ++b) red[warp][b][lane] = acc[b];
    __syncthreads();

    if (tid < 256) {
        const int b = tid >> 5;
        float s = 0.f;
        #pragma unroll
        for (int w2 = 0; w2 < 16; ++w2) s += red[w2][b][lane];
        g_part[hq * BL + (bg * 8 + b) * LL + l] = s;
        __threadfence();                  // release partials before counter bump
    }
    __syncthreads();

    if (tid == 0) {
        // wraps 0,1,2,3 -> 0 : self-resetting across graph replays
        unsigned old = atomicInc(&g_cnt[(bg << 5) | lt], 3u);
        s_last = (old == 3u);
        if (s_last) __threadfence();      // acquire before reading peers' partials
    }
    __syncthreads();

    if (s_last && tid < 256) {
        const int b   = tid >> 5;
        const int idx = (bg * 8 + b) * LL + l;
        float s = __ldg(&bias[l])
                + __ldcg(&g_part[0 * BL + idx])
                + __ldcg(&g_part[1 * BL + idx])
                + __ldcg(&g_part[2 * BL + idx])
                + __ldcg(&g_part[3 * BL + idx]);
        g_gate[idx] = 1.0f / (1.0f + __expf(-s));
    }
}

// ---------------------------------------------------------------------------
// Stream: exact R2 form (proven 56.6us). One block per (b,l) row, 256 thr.
// ---------------------------------------------------------------------------
__global__ __launch_bounds__(256, 8)
void stream_kernel(const float4* __restrict__ graph,
                   const float4* __restrict__ query,
                   float4* __restrict__ out)
{
    const int bl  = blockIdx.x;
    const int b   = bl >> 10;
    const int tid = threadIdx.x;

    const float g = __ldg(&g_gate[bl]);

    const float4 v = __ldcs(&graph[(long long)bl * (DG / 4) + tid]);
    const float4 q = __ldg(&query[b * (HH / 4) + tid]);

    float4* o = out + (long long)bl * (OUTW / 4);
    __stcs(&o[tid],            make_float4(v.x * g, v.y * g, v.z * g, v.w * g));
    __stcs(&o[(DG / 4) + tid], q);
}

extern "C" void kernel_launch(void* const* d_in, const int* in_sizes, int n_in,
                              void* d_out, int out_size)
{
    const float* graph = (const float*)d_in[0];
    const float* query = (const float*)d_in[1];
    const float* W     = (const float*)d_in[2];
    const float* bias  = (const float*)d_in[3];
    float* out = (float*)d_out;

    gate_kernel<<<512, 512>>>(query, W, bias);
    stream_kernel<<<BL, 256>>>((const float4*)graph,
                               (const float4*)query,
                               (float4*)out);

    (void)in_sizes; (void)n_in; (void)out_size;
}